// round 5
// baseline (speedup 1.0000x reference)
#include <cuda_runtime.h>

// Global accumulators (zero-initialized at module load; reset by the last
// block of every run so graph replays are deterministic). No device allocs.
__device__ double g_sum0;                  // sum of picked log-probs, class 0
__device__ double g_sum1;                  // sum of picked log-probs, class 1
__device__ unsigned long long g_cnt1;      // count of targets == 1
__device__ unsigned int g_blocks_done;     // retirement counter

__device__ __forceinline__ void proc_pair(float4 a, int2 t,
                                          float& s0, float& s1, int& c1) {
    // token 0 of the pair
    {
        float m   = fmaxf(a.x, a.y);
        float d   = -fabsf(a.x - a.y);
        float lse = m + __logf(1.0f + __expf(d));
        if (t.x != 0) { s1 += a.y - lse; c1 += 1; }
        else          { s0 += a.x - lse; }
    }
    // token 1 of the pair
    {
        float m   = fmaxf(a.z, a.w);
        float d   = -fabsf(a.z - a.w);
        float lse = m + __logf(1.0f + __expf(d));
        if (t.y != 0) { s1 += a.w - lse; c1 += 1; }
        else          { s0 += a.z - lse; }
    }
}

// Single fused kernel, warp-coalesced layout:
// Unit of work = a token PAIR (one float4 of x + one int2 of targets).
// Thread's k-th pair index = blockIdx*1024 + k*256 + threadIdx (k=0..3),
// so every LDG.128 / LDG.64 is 32 contiguous lanes -> minimal L1 wavefronts.
__global__ __launch_bounds__(256) void nll_fused_kernel(
    const float* __restrict__ x,
    const int* __restrict__ targets,
    long long n_tokens,
    float* __restrict__ out)
{
    const long long n_pairs    = n_tokens >> 1;            // tokens are even (2048-divisible grids); tail loop covers odd
    const long long block_base = (long long)blockIdx.x * 1024;  // pairs per block = 4 * 256

    float s0 = 0.0f, s1 = 0.0f;
    int   c1 = 0;

    const float4* x4 = reinterpret_cast<const float4*>(x);
    const int2*   t2 = reinterpret_cast<const int2*>(targets);

    const long long p0 = block_base + 0 * 256 + threadIdx.x;
    const long long p1 = block_base + 1 * 256 + threadIdx.x;
    const long long p2 = block_base + 2 * 256 + threadIdx.x;
    const long long p3 = block_base + 3 * 256 + threadIdx.x;

    if (p3 < n_pairs) {
        // front-batch all 8 coalesced loads
        float4 a0 = x4[p0];
        float4 a1 = x4[p1];
        float4 a2 = x4[p2];
        float4 a3 = x4[p3];
        int2   b0 = t2[p0];
        int2   b1 = t2[p1];
        int2   b2 = t2[p2];
        int2   b3 = t2[p3];

        proc_pair(a0, b0, s0, s1, c1);
        proc_pair(a1, b1, s0, s1, c1);
        proc_pair(a2, b2, s0, s1, c1);
        proc_pair(a3, b3, s0, s1, c1);
    } else {
        // generic tail: per-pair, then the possible odd last token
        long long ps[4] = {p0, p1, p2, p3};
        #pragma unroll
        for (int k = 0; k < 4; k++) {
            if (ps[k] < n_pairs) {
                proc_pair(x4[ps[k]], t2[ps[k]], s0, s1, c1);
            }
        }
        // odd trailing token handled by thread 0 of the last block
        if ((n_tokens & 1) && blockIdx.x == gridDim.x - 1 && threadIdx.x == 0) {
            long long i = n_tokens - 1;
            float x0 = x[2 * i], x1v = x[2 * i + 1];
            int   t  = targets[i];
            float m   = fmaxf(x0, x1v);
            float d   = -fabsf(x0 - x1v);
            float lse = m + __logf(1.0f + __expf(d));
            if (t != 0) { s1 += x1v - lse; c1 += 1; }
            else        { s0 += x0 - lse; }
        }
    }

    // warp reduction
    #pragma unroll
    for (int off = 16; off > 0; off >>= 1) {
        s0 += __shfl_down_sync(0xFFFFFFFFu, s0, off);
        s1 += __shfl_down_sync(0xFFFFFFFFu, s1, off);
        c1 += __shfl_down_sync(0xFFFFFFFFu, c1, off);
    }

    __shared__ float sh0[8];
    __shared__ float sh1[8];
    __shared__ int   shc[8];
    const int lane = threadIdx.x & 31;
    const int wid  = threadIdx.x >> 5;
    if (lane == 0) { sh0[wid] = s0; sh1[wid] = s1; shc[wid] = c1; }
    __syncthreads();

    __shared__ bool is_last;
    if (wid == 0) {
        const int nw = blockDim.x >> 5;
        s0 = (lane < nw) ? sh0[lane] : 0.0f;
        s1 = (lane < nw) ? sh1[lane] : 0.0f;
        c1 = (lane < nw) ? shc[lane] : 0;
        #pragma unroll
        for (int off = 4; off > 0; off >>= 1) {
            s0 += __shfl_down_sync(0xFFFFFFFFu, s0, off);
            s1 += __shfl_down_sync(0xFFFFFFFFu, s1, off);
            c1 += __shfl_down_sync(0xFFFFFFFFu, c1, off);
        }
        if (lane == 0) {
            atomicAdd(&g_sum0, (double)s0);
            atomicAdd(&g_sum1, (double)s1);
            atomicAdd(&g_cnt1, (unsigned long long)c1);
            __threadfence();
            unsigned int done = atomicAdd(&g_blocks_done, 1u);
            is_last = (done == gridDim.x - 1u);
        }
    }
    __syncthreads();

    // Last block to retire finalizes and resets globals for the next replay.
    if (is_last && threadIdx.x == 0) {
        __threadfence();
        double sum0 = g_sum0;
        double sum1 = g_sum1;
        unsigned long long n1 = g_cnt1;
        unsigned long long n0 = (unsigned long long)n_tokens - n1;
        double r = (n1 > 0) ? (-sum1 / (double)n1) : 0.0;
        double p = (n0 > 0) ? (-sum0 / (double)n0) : 0.0;
        out[0] = (float)(p + r);
        // reset for next graph replay
        g_sum0 = 0.0;
        g_sum1 = 0.0;
        g_cnt1 = 0ull;
        g_blocks_done = 0u;
    }
}

extern "C" void kernel_launch(void* const* d_in, const int* in_sizes, int n_in,
                              void* d_out, int out_size) {
    const float* x       = (const float*)d_in[0];
    const int*   targets = (const int*)d_in[1];
    float*       out     = (float*)d_out;

    const long long n_tokens = (long long)in_sizes[1];

    // 2048 tokens (1024 pairs) per block
    const long long n_pairs = (n_tokens + 1) / 2;
    const int block = 256;
    const int grid  = (int)((n_pairs + 1023) / 1024);
    nll_fused_kernel<<<grid, block>>>(x, targets, n_tokens, out);
}